// round 5
// baseline (speedup 1.0000x reference)
#include <cuda_runtime.h>
#include <cstdint>

// Problem constants
#define B      16
#define FOUT   64
#define FIN    192          // 3*FOUT
#define IMG    64
#define HW     4096         // IMG*IMG
#define LDIM   512
#define NCALLS 16
#define EPSV   1e-5f

// d_out layout: [clipped 16*3*4096][embs 17*16*64*4096][raw 16*3*4096]
#define CLIP_N   (B*3*HW)                 // 196608
#define EMBS_N   ((NCALLS+1)*B*FOUT*HW)   // 71303168
#define SLICE_N  ((long long)B*FOUT*HW)   // 4194304 per time slice

// Scratch (device globals are the allowed scratch mechanism)
__device__ float g_P[(size_t)B*FIN*HW];    // 48 MB: [b][c' (0..191)][hw]
__device__ float g_w[(size_t)B*FOUT*FIN];  // 3 MB : raw w, [b][o][c]
__device__ float g_bv[B*FOUT];
__device__ float g_mu[B*FIN];
__device__ float g_rstd[B*FIN];

// ---------------------------------------------------------------------------
// init: embs[0] = 0 except [b][0][32][32] = 1
// ---------------------------------------------------------------------------
__global__ void k_init(float* __restrict__ embs0) {
    int idx = blockIdx.x * blockDim.x + threadIdx.x;   // 4096 x 1024 covers slice
    if (idx >= (int)SLICE_N) return;
    int ch  = (idx >> 12) & 63;
    int pix = idx & 4095;
    embs0[idx] = (ch == 0 && pix == (32*IMG + 32)) ? 1.0f : 0.0f;
}

// ---------------------------------------------------------------------------
// w = lat @ Wk + bk   (16 x 12288, K=512)
// ---------------------------------------------------------------------------
__global__ void k_prep_w(const float* __restrict__ lat,
                         const float* __restrict__ Wk,
                         const float* __restrict__ bk) {
    __shared__ float latS[LDIM];
    int b = blockIdx.y;
    for (int i = threadIdx.x; i < LDIM; i += blockDim.x) latS[i] = lat[b*LDIM + i];
    __syncthreads();
    int j = blockIdx.x * blockDim.x + threadIdx.x;     // 0..12287
    if (j >= FOUT*FIN) return;
    float s = bk[j];
    #pragma unroll 4
    for (int l = 0; l < LDIM; l++)
        s = fmaf(latS[l], Wk[(size_t)l*(FOUT*FIN) + j], s);
    g_w[(size_t)b*(FOUT*FIN) + j] = s;                 // j = o*192 + c
}

// b = lat @ Wb + bb   (16 x 64)
__global__ void k_prep_b(const float* __restrict__ lat,
                         const float* __restrict__ Wb,
                         const float* __restrict__ bb) {
    __shared__ float latS[LDIM];
    int b = blockIdx.x;
    for (int i = threadIdx.x; i < LDIM; i += blockDim.x) latS[i] = lat[b*LDIM + i];
    __syncthreads();
    int o = threadIdx.x;
    if (o >= FOUT) return;
    float s = bb[o];
    #pragma unroll 4
    for (int l = 0; l < LDIM; l++)
        s = fmaf(latS[l], Wb[l*FOUT + o], s);
    g_bv[b*FOUT + o] = s;
}

// ---------------------------------------------------------------------------
// stats: one block per (b, c). Computes gx,gy (sobel SAME zero pad, cross-
// correlation), writes out/gx/gy into g_P, and per-channel mu/rstd via
// TWO-PASS fp32 (matches jnp.var numerics, no FP64 in hot path).
// ---------------------------------------------------------------------------
__global__ void __launch_bounds__(256) k_stats(const float* __restrict__ embs_t) {
    __shared__ float t[66*68];               // halo tile, pitch 68
    __shared__ float redS[8][3];
    __shared__ float muS[3];
    int c = blockIdx.x, b = blockIdx.y;
    int tx = threadIdx.x;
    int wid = tx >> 5, lid = tx & 31;

    for (int i = tx; i < 66*68; i += 256) t[i] = 0.0f;
    __syncthreads();
    const float* src = embs_t + ((size_t)b*FOUT + c)*HW;
    for (int i = tx; i < HW; i += 256)
        t[((i >> 6) + 1)*68 + (i & 63) + 1] = src[i];
    __syncthreads();

    float* Pb = g_P + ((size_t)b*FIN +       c)*HW;
    float* Px = g_P + ((size_t)b*FIN +  64 + c)*HW;
    float* Py = g_P + ((size_t)b*FIN + 128 + c)*HW;

    float vv[16], gxv[16], gyv[16];
    float s0 = 0.f, sx = 0.f, sy = 0.f;
    #pragma unroll
    for (int j = 0; j < 16; j++) {
        int i = tx + 256*j;
        int p = ((i >> 6) + 1)*68 + (i & 63) + 1;
        float v   = t[p];
        float a00 = t[p-68-1], a01 = t[p-68], a02 = t[p-68+1];
        float a10 = t[p-1],                   a12 = t[p+1];
        float a20 = t[p+68-1], a21 = t[p+68], a22 = t[p+68+1];
        float gx = ((a02 - a00) + 2.0f*(a12 - a10) + (a22 - a20)) * 0.125f;
        float gy = ((a20 - a00) + 2.0f*(a21 - a01) + (a22 - a02)) * 0.125f;
        Pb[i] = v; Px[i] = gx; Py[i] = gy;
        vv[j] = v; gxv[j] = gx; gyv[j] = gy;
        s0 += v; sx += gx; sy += gy;
    }
    // pass 1 reduce: means
    #pragma unroll
    for (int off = 16; off; off >>= 1) {
        s0 += __shfl_down_sync(0xffffffffu, s0, off);
        sx += __shfl_down_sync(0xffffffffu, sx, off);
        sy += __shfl_down_sync(0xffffffffu, sy, off);
    }
    if (lid == 0) { redS[wid][0] = s0; redS[wid][1] = sx; redS[wid][2] = sy; }
    __syncthreads();
    if (tx < 3) {
        float a = 0.f;
        #pragma unroll
        for (int w = 0; w < 8; w++) a += redS[w][tx];
        muS[tx] = a * (1.0f/(float)HW);
    }
    __syncthreads();
    float mu0 = muS[0], mux = muS[1], muy = muS[2];

    // pass 2: centered sums of squares (from registers)
    float q0 = 0.f, qx = 0.f, qy = 0.f;
    #pragma unroll
    for (int j = 0; j < 16; j++) {
        float d0 = vv[j]  - mu0; q0 = fmaf(d0, d0, q0);
        float dx = gxv[j] - mux; qx = fmaf(dx, dx, qx);
        float dy = gyv[j] - muy; qy = fmaf(dy, dy, qy);
    }
    #pragma unroll
    for (int off = 16; off; off >>= 1) {
        q0 += __shfl_down_sync(0xffffffffu, q0, off);
        qx += __shfl_down_sync(0xffffffffu, qx, off);
        qy += __shfl_down_sync(0xffffffffu, qy, off);
    }
    if (lid == 0) { redS[wid][0] = q0; redS[wid][1] = qx; redS[wid][2] = qy; }
    __syncthreads();
    if (tx < 3) {
        float a = 0.f;
        #pragma unroll
        for (int w = 0; w < 8; w++) a += redS[w][tx];
        float var = a * (1.0f/(float)HW);
        float rs = 1.0f / sqrtf(var + EPSV);
        g_mu  [b*FIN + tx*64 + c] = muS[tx];
        g_rstd[b*FIN + tx*64 + c] = rs;
    }
}

// ---------------------------------------------------------------------------
// GEMM step (prep fused, W streamed in 64-ch chunks for occ 3):
// per CTA = (batch b, 128-pixel tile), all 64 outputs.
// W'[o,c] = leak*w[o,c]*rstd[b,c]     (scaled while filling Wch per chunk)
// b'[o]   = leak*bvec[o] - sum_c W'[o,c]*mu[b,c] (partials accumulated per chunk)
// out_{t+1} = out_t + W'(64x192) * P_raw(192x128) + b'
// smem: Wch[64][64] + Psh[64][128] + rssh[192] + mush[192] + bsh4[64][4]
//     = (4096 + 8192 + 192 + 192 + 256)*4 = 51,712 B
// ---------------------------------------------------------------------------
#define TP 128
#define SMEM_GEMM ((64*FOUT + 64*TP + FIN + FIN + FOUT*4) * 4)

__global__ void __launch_bounds__(256, 3) k_gemm(const float* __restrict__ embs_t,
                                                 float* __restrict__ embs_t1,
                                                 const float* __restrict__ lf) {
    extern __shared__ float sm[];
    float* Wch  = sm;                          // [64 ch][64 o] current chunk
    float* Psh  = Wch  + 64*FOUT;              // [64][128]
    float* rssh = Psh  + 64*TP;                // [192] leak*rstd
    float* mush = rssh + FIN;                  // [192] mu
    float* bsh4 = mush + FIN;                  // [64][4] beff partials

    int b      = blockIdx.y;
    int p_base = blockIdx.x * TP;
    int tx = threadIdx.x;
    int og = tx >> 4, pg = tx & 15;
    int o0 = og * 4, p0 = pg * 8;
    int bo = tx >> 2, bq = tx & 3;             // beff-partial role: output bo, quarter bq

    float leak = fminf(fmaxf(lf[0], 0.001f), 1000.0f);

    // per-channel scale factors + means
    for (int i = tx; i < FIN; i += 256) {
        rssh[i] = g_rstd[b*FIN + i] * leak;
        mush[i] = g_mu[b*FIN + i];
    }

    float acc[4][8];
    #pragma unroll
    for (int i = 0; i < 4; i++)
        #pragma unroll
        for (int j = 0; j < 8; j++) acc[i][j] = 0.0f;
    float bpart = 0.0f;

    const float* wb = g_w + (size_t)b*FOUT*FIN;
    const float* Pg = g_P + (size_t)b*FIN*HW;

    for (int ck = 0; ck < 3; ck++) {
        __syncthreads();   // protects rssh/mush on first iter, Wch/Psh reuse after
        // stream this chunk of scaled weights (coalesced read, transposed store)
        #pragma unroll
        for (int i = 0; i < 16; i++) {
            int f  = tx + 256*i;               // < 4096
            int o  = f >> 6;
            int cl = f & 63;
            Wch[cl*FOUT + o] = wb[(size_t)o*FIN + ck*64 + cl] * rssh[ck*64 + cl];
        }
        // stream P chunk
        #pragma unroll
        for (int i = 0; i < 8; i++) {
            int f  = tx + 256*i;               // float4 index, < 2048
            int r  = f >> 5;
            int c4 = f & 31;
            float4 v = *(const float4*)(Pg + ((size_t)(ck*64 + r))*HW + p_base + c4*4);
            *(float4*)(Psh + r*TP + c4*4) = v;
        }
        __syncthreads();
        #pragma unroll 4
        for (int k = 0; k < 64; k++) {
            const float4 av = *(const float4*)(Wch + k*FOUT + o0);
            const float4 b0 = *(const float4*)(Psh + k*TP + p0);
            const float4 b1 = *(const float4*)(Psh + k*TP + p0 + 4);
            float aa[4] = {av.x, av.y, av.z, av.w};
            float bv[8] = {b0.x, b0.y, b0.z, b0.w, b1.x, b1.y, b1.z, b1.w};
            #pragma unroll
            for (int i = 0; i < 4; i++)
                #pragma unroll
                for (int j = 0; j < 8; j++)
                    acc[i][j] = fmaf(aa[i], bv[j], acc[i][j]);
        }
        // beff partial for this chunk (uses Wch before next overwrite)
        #pragma unroll 4
        for (int j = 0; j < 16; j++) {
            int cl = bq*16 + j;
            bpart = fmaf(Wch[cl*FOUT + bo], mush[ck*64 + cl], bpart);
        }
    }

    bsh4[bo*4 + bq] = bpart;
    __syncthreads();

    float beff[4];
    #pragma unroll
    for (int i = 0; i < 4; i++) {
        int o = o0 + i;
        beff[i] = leak * g_bv[b*FOUT + o]
                - (bsh4[o*4+0] + bsh4[o*4+1] + bsh4[o*4+2] + bsh4[o*4+3]);
    }

    #pragma unroll
    for (int i = 0; i < 4; i++) {
        size_t off = ((size_t)b*FOUT + o0 + i)*HW + p_base + p0;
        float4 old0 = *(const float4*)(embs_t + off);
        float4 old1 = *(const float4*)(embs_t + off + 4);
        float4 r0, r1;
        r0.x = old0.x + acc[i][0] + beff[i];
        r0.y = old0.y + acc[i][1] + beff[i];
        r0.z = old0.z + acc[i][2] + beff[i];
        r0.w = old0.w + acc[i][3] + beff[i];
        r1.x = old1.x + acc[i][4] + beff[i];
        r1.y = old1.y + acc[i][5] + beff[i];
        r1.z = old1.z + acc[i][6] + beff[i];
        r1.w = old1.w + acc[i][7] + beff[i];
        *(float4*)(embs_t1 + off)     = r0;
        *(float4*)(embs_t1 + off + 4) = r1;
    }
}

// ---------------------------------------------------------------------------
// finalize: clipped + raw from embs[16][:, :3]
// ---------------------------------------------------------------------------
__global__ void k_final(const float* __restrict__ embs16,
                        float* __restrict__ clipd,
                        float* __restrict__ rawd) {
    int idx = blockIdx.x * blockDim.x + threadIdx.x;
    if (idx >= CLIP_N) return;
    int b   = idx / (3*HW);
    int rem = idx - b*(3*HW);
    int c   = rem >> 12;
    int pix = rem & 4095;
    float v = embs16[((size_t)b*FOUT + c)*HW + pix];
    rawd[idx]  = v;
    clipd[idx] = fminf(fmaxf(v, -1.0f), 1.0f);
}

// ---------------------------------------------------------------------------
extern "C" void kernel_launch(void* const* d_in, const int* in_sizes, int n_in,
                              void* d_out, int out_size) {
    const float* lat = (const float*)d_in[0];
    const float* Wk  = (const float*)d_in[1];
    const float* bk  = (const float*)d_in[2];
    const float* Wb  = (const float*)d_in[3];
    const float* bb  = (const float*)d_in[4];
    const float* lf  = (const float*)d_in[5];

    float* outp  = (float*)d_out;
    float* clipd = outp;
    float* embs  = outp + CLIP_N;
    float* rawd  = outp + CLIP_N + EMBS_N;

    cudaFuncSetAttribute(k_gemm, cudaFuncAttributeMaxDynamicSharedMemorySize, SMEM_GEMM);

    k_init  <<<4096, 1024>>>(embs);
    k_prep_w<<<dim3(48, B), 256>>>(lat, Wk, bk);
    k_prep_b<<<B, 64>>>(lat, Wb, bb);

    for (int t = 0; t < NCALLS; t++) {
        const float* et  = embs + (long long)t * SLICE_N;
        float*       et1 = embs + (long long)(t+1) * SLICE_N;
        k_stats<<<dim3(FOUT, B), 256>>>(et);
        k_gemm <<<dim3(HW/TP, B), 256, SMEM_GEMM>>>(et, et1, lf);
    }
    k_final<<<(CLIP_N + 255)/256, 256>>>(embs + (long long)NCALLS * SLICE_N, clipd, rawd);
}

// round 6
// speedup vs baseline: 1.1402x; 1.1402x over previous
#include <cuda_runtime.h>
#include <cstdint>

// Problem constants
#define B      16
#define FOUT   64
#define FIN    192          // 3*FOUT
#define IMG    64
#define HW     4096         // IMG*IMG
#define LDIM   512
#define NCALLS 16
#define EPSV   1e-5f

// d_out layout: [clipped 16*3*4096][embs 17*16*64*4096][raw 16*3*4096]
#define CLIP_N   (B*3*HW)                 // 196608
#define EMBS_N   ((NCALLS+1)*B*FOUT*HW)   // 71303168
#define SLICE_N  ((long long)B*FOUT*HW)   // 4194304 per time slice

// Scratch (device globals are the allowed scratch mechanism)
__device__ float g_P[(size_t)B*FIN*HW];    // 48 MB: [b][c' (0..191)][hw]
__device__ float g_w[(size_t)B*FOUT*FIN];  // 3 MB : raw w, [b][o][c]
__device__ float g_bv[B*FOUT];
__device__ float g_mu[B*FIN];
__device__ float g_rstd[B*FIN];

// ---------------------------------------------------------------------------
// init: embs[0] = 0 except [b][0][32][32] = 1
// ---------------------------------------------------------------------------
__global__ void k_init(float* __restrict__ embs0) {
    int idx = blockIdx.x * blockDim.x + threadIdx.x;   // 4096 x 1024 covers slice
    if (idx >= (int)SLICE_N) return;
    int ch  = (idx >> 12) & 63;
    int pix = idx & 4095;
    embs0[idx] = (ch == 0 && pix == (32*IMG + 32)) ? 1.0f : 0.0f;
}

// ---------------------------------------------------------------------------
// merged prep: blocks 0..47: w = lat@Wk + bk for ALL batches (Wk read once)
//              block 48    : bvec = lat@Wb + bb for all batches
// ---------------------------------------------------------------------------
__global__ void __launch_bounds__(256) k_prep(const float* __restrict__ lat,
                                              const float* __restrict__ Wk,
                                              const float* __restrict__ bk,
                                              const float* __restrict__ Wb,
                                              const float* __restrict__ bb) {
    __shared__ float latS[B][LDIM];   // 32 KB
    int tx = threadIdx.x;
    for (int i = tx; i < B*LDIM; i += 256) latS[i >> 9][i & 511] = lat[i];
    __syncthreads();

    if (blockIdx.x < 48) {
        int j = blockIdx.x * 256 + tx;           // 0..12287  (= o*192 + c)
        float acc[B];
        float bkj = bk[j];
        #pragma unroll
        for (int b = 0; b < B; b++) acc[b] = bkj;
        for (int l = 0; l < LDIM; l++) {
            float wv = Wk[(size_t)l*(FOUT*FIN) + j];
            #pragma unroll
            for (int b = 0; b < B; b++) acc[b] = fmaf(latS[b][l], wv, acc[b]);
        }
        #pragma unroll
        for (int b = 0; b < B; b++) g_w[(size_t)b*FOUT*FIN + j] = acc[b];
    } else {
        int o = tx & 63, bg = tx >> 6;
        for (int bi = bg; bi < B; bi += 4) {
            float s = bb[o];
            #pragma unroll 4
            for (int l = 0; l < LDIM; l++)
                s = fmaf(latS[bi][l], Wb[l*FOUT + o], s);
            g_bv[bi*FOUT + o] = s;
        }
    }
}

// ---------------------------------------------------------------------------
// stats: one block per (b, c). Row-strip float4 stencil: thread = (row tx>>2,
// quarter tx&3, 16 px). Sobel SAME zero pad (cross-correlation). Writes
// out/gx/gy into g_P. Stats: gx/gy single-pass E[x^2] (means ~0, safe);
// v two-pass from registers.
// ---------------------------------------------------------------------------
__global__ void __launch_bounds__(256) k_stats(const float* __restrict__ embs_t) {
    __shared__ float t[66*68];               // halo tile, pitch 68 (17.9 KB)
    __shared__ float redS[8][5];
    __shared__ float muS[1];
    int c = blockIdx.x, b = blockIdx.y;
    int tx = threadIdx.x;
    int wid = tx >> 5, lid = tx & 31;

    // zero halo + fill interior (vectorized read)
    for (int i = tx; i < (66*68)/4; i += 256)
        *(float4*)(t + i*4) = make_float4(0.f, 0.f, 0.f, 0.f);
    __syncthreads();
    const float4* src4 = (const float4*)(embs_t + ((size_t)b*FOUT + c)*HW);
    #pragma unroll
    for (int i = 0; i < 4; i++) {
        int f = tx + 256*i;                  // < 1024
        float4 v = src4[f];
        int px = f*4, h = px >> 6, w = px & 63;
        float* d = t + (h+1)*68 + (w+1);
        d[0] = v.x; d[1] = v.y; d[2] = v.z; d[3] = v.w;
    }
    __syncthreads();

    int r  = tx >> 2;                        // pixel row 0..63
    int q  = tx & 3;
    int c0 = q * 16;                         // t-col base (covers pixel cols c0..c0+15)

    float top[18], mid[18], bot[18];
    {
        const float* t0 = t + r*68     + c0;
        const float* t1 = t + (r+1)*68 + c0;
        const float* t2 = t + (r+2)*68 + c0;
        #pragma unroll
        for (int j4 = 0; j4 < 4; j4++) {
            *(float4*)(top + j4*4) = *(const float4*)(t0 + j4*4);
            *(float4*)(mid + j4*4) = *(const float4*)(t1 + j4*4);
            *(float4*)(bot + j4*4) = *(const float4*)(t2 + j4*4);
        }
        top[16] = t0[16]; top[17] = t0[17];
        mid[16] = t1[16]; mid[17] = t1[17];
        bot[16] = t2[16]; bot[17] = t2[17];
    }

    float* Pb = g_P + ((size_t)b*FIN +       c)*HW + r*64 + c0;
    float* Px = g_P + ((size_t)b*FIN +  64 + c)*HW + r*64 + c0;
    float* Py = g_P + ((size_t)b*FIN + 128 + c)*HW + r*64 + c0;

    float gxr[16], gyr[16];
    float s0 = 0.f, sx = 0.f, qx = 0.f, sy = 0.f, qy = 0.f;
    #pragma unroll
    for (int j = 0; j < 16; j++) {
        float v  = mid[j+1];
        float gx = ((top[j+2] - top[j]) + 2.0f*(mid[j+2] - mid[j]) + (bot[j+2] - bot[j])) * 0.125f;
        float gy = ((bot[j] - top[j]) + 2.0f*(bot[j+1] - top[j+1]) + (bot[j+2] - top[j+2])) * 0.125f;
        gxr[j] = gx; gyr[j] = gy;
        s0 += v;
        sx += gx; qx = fmaf(gx, gx, qx);
        sy += gy; qy = fmaf(gy, gy, qy);
    }
    #pragma unroll
    for (int j4 = 0; j4 < 4; j4++) {
        *(float4*)(Pb + j4*4) = *(const float4*)(mid + 1 + j4*4 - 0);   // unaligned src in regs: do scalar pack
    }
    // (register-source stores: write explicitly, compiler vectorizes dest)
    #pragma unroll
    for (int j = 0; j < 16; j++) Pb[j] = mid[j+1];
    #pragma unroll
    for (int j4 = 0; j4 < 4; j4++) {
        *(float4*)(Px + j4*4) = make_float4(gxr[j4*4], gxr[j4*4+1], gxr[j4*4+2], gxr[j4*4+3]);
        *(float4*)(Py + j4*4) = make_float4(gyr[j4*4], gyr[j4*4+1], gyr[j4*4+2], gyr[j4*4+3]);
    }

    // reduce s0, sx, qx, sy, qy
    #pragma unroll
    for (int off = 16; off; off >>= 1) {
        s0 += __shfl_down_sync(0xffffffffu, s0, off);
        sx += __shfl_down_sync(0xffffffffu, sx, off);
        qx += __shfl_down_sync(0xffffffffu, qx, off);
        sy += __shfl_down_sync(0xffffffffu, sy, off);
        qy += __shfl_down_sync(0xffffffffu, qy, off);
    }
    if (lid == 0) {
        redS[wid][0]=s0; redS[wid][1]=sx; redS[wid][2]=qx; redS[wid][3]=sy; redS[wid][4]=qy;
    }
    __syncthreads();
    if (tx == 0) {
        float a0=0,a1=0,a2=0,a3=0,a4=0;
        #pragma unroll
        for (int w = 0; w < 8; w++) {
            a0+=redS[w][0]; a1+=redS[w][1]; a2+=redS[w][2]; a3+=redS[w][3]; a4+=redS[w][4];
        }
        const float inv = 1.0f/(float)HW;
        float mu0 = a0*inv;
        muS[0] = mu0;
        float mux = a1*inv, varx = a2*inv - mux*mux;
        float muy = a3*inv, vary = a4*inv - muy*muy;
        g_mu  [b*FIN +  64 + c] = mux;
        g_rstd[b*FIN +  64 + c] = 1.0f/sqrtf(varx + EPSV);
        g_mu  [b*FIN + 128 + c] = muy;
        g_rstd[b*FIN + 128 + c] = 1.0f/sqrtf(vary + EPSV);
        g_mu  [b*FIN + c] = mu0;
    }
    __syncthreads();
    float mu0 = muS[0];
    float q0 = 0.f;
    #pragma unroll
    for (int j = 0; j < 16; j++) {
        float d = mid[j+1] - mu0; q0 = fmaf(d, d, q0);
    }
    #pragma unroll
    for (int off = 16; off; off >>= 1)
        q0 += __shfl_down_sync(0xffffffffu, q0, off);
    if (lid == 0) redS[wid][0] = q0;
    __syncthreads();
    if (tx == 0) {
        float a = 0.f;
        #pragma unroll
        for (int w = 0; w < 8; w++) a += redS[w][0];
        float var0 = a * (1.0f/(float)HW);
        g_rstd[b*FIN + c] = 1.0f/sqrtf(var0 + EPSV);
    }
}

// ---------------------------------------------------------------------------
// GEMM step (prep fused). W chunk stored o-major/k-fast with pitch 68:
// conflict-free fill (straight scaled copy) and conflict-free mainloop reads.
// out_{t+1} = out_t + W'(64x192) * P_raw(192x128) + b'
// smem: Wch[64][68] + Psh[64][128] + rssh[192] + mush[192] + bsh4[64][4]
//     = (4352 + 8192 + 192 + 192 + 256)*4 = 52,736 B
// ---------------------------------------------------------------------------
#define TP 128
#define WPITCH 68
#define SMEM_GEMM ((64*WPITCH + 64*TP + FIN + FIN + FOUT*4) * 4)

__global__ void __launch_bounds__(256, 2) k_gemm(const float* __restrict__ embs_t,
                                                 float* __restrict__ embs_t1,
                                                 const float* __restrict__ lf) {
    extern __shared__ float sm[];
    float* Wch  = sm;                          // [64 o][68] k-fast, pitch 68
    float* Psh  = Wch  + 64*WPITCH;            // [64 k][128 px]
    float* rssh = Psh  + 64*TP;                // [192] leak*rstd
    float* mush = rssh + FIN;                  // [192] mu
    float* bsh4 = mush + FIN;                  // [64][4] beff partials

    int b      = blockIdx.y;
    int p_base = blockIdx.x * TP;
    int tx = threadIdx.x;
    int og = tx >> 4, pg = tx & 15;
    int o0 = og * 4, p0 = pg * 8;
    int bo = tx >> 2, bq = tx & 3;             // beff role: output bo, quarter bq

    float leak = fminf(fmaxf(lf[0], 0.001f), 1000.0f);

    for (int i = tx; i < FIN; i += 256) {
        rssh[i] = g_rstd[b*FIN + i] * leak;
        mush[i] = g_mu[b*FIN + i];
    }

    float acc[4][8];
    #pragma unroll
    for (int i = 0; i < 4; i++)
        #pragma unroll
        for (int j = 0; j < 8; j++) acc[i][j] = 0.0f;
    float bpart = 0.0f;

    const float* wb = g_w + (size_t)b*FOUT*FIN;
    const float* Pg = g_P + (size_t)b*FIN*HW;

    for (int ck = 0; ck < 3; ck++) {
        __syncthreads();   // rssh/mush ready (iter 0); Wch/Psh drained (iters 1,2)
        // W chunk: coalesced LDG.128, scaled, STS.128 (no transpose, pitch 68)
        #pragma unroll
        for (int i = 0; i < 4; i++) {
            int f4  = tx + 256*i;              // < 1024
            int o   = f4 >> 4;
            int cl4 = (f4 & 15) * 4;
            float4 v = *(const float4*)(wb + (size_t)o*FIN + ck*64 + cl4);
            v.x *= rssh[ck*64 + cl4];
            v.y *= rssh[ck*64 + cl4 + 1];
            v.z *= rssh[ck*64 + cl4 + 2];
            v.w *= rssh[ck*64 + cl4 + 3];
            *(float4*)(Wch + o*WPITCH + cl4) = v;
        }
        // P chunk
        #pragma unroll
        for (int i = 0; i < 8; i++) {
            int f  = tx + 256*i;               // float4 index, < 2048
            int rr = f >> 5;
            int c4 = f & 31;
            float4 v = *(const float4*)(Pg + ((size_t)(ck*64 + rr))*HW + p_base + c4*4);
            *(float4*)(Psh + rr*TP + c4*4) = v;
        }
        __syncthreads();

        #pragma unroll 2
        for (int kq = 0; kq < 16; kq++) {
            float aO[4][4];
            #pragma unroll
            for (int i = 0; i < 4; i++)
                *(float4*)aO[i] = *(const float4*)(Wch + (o0 + i)*WPITCH + kq*4);
            #pragma unroll
            for (int sub = 0; sub < 4; sub++) {
                int k = kq*4 + sub;
                const float4 b0 = *(const float4*)(Psh + k*TP + p0);
                const float4 b1 = *(const float4*)(Psh + k*TP + p0 + 4);
                float bv[8] = {b0.x, b0.y, b0.z, b0.w, b1.x, b1.y, b1.z, b1.w};
                #pragma unroll
                for (int i = 0; i < 4; i++)
                    #pragma unroll
                    for (int j = 0; j < 8; j++)
                        acc[i][j] = fmaf(aO[i][sub], bv[j], acc[i][j]);
            }
        }
        // beff partial for this chunk (reads Wch before next overwrite)
        #pragma unroll 4
        for (int j = 0; j < 16; j++) {
            int cl = bq*16 + j;
            bpart = fmaf(Wch[bo*WPITCH + cl], mush[ck*64 + cl], bpart);
        }
    }

    bsh4[bo*4 + bq] = bpart;
    __syncthreads();

    float beff[4];
    #pragma unroll
    for (int i = 0; i < 4; i++) {
        int o = o0 + i;
        beff[i] = leak * g_bv[b*FOUT + o]
                - (bsh4[o*4+0] + bsh4[o*4+1] + bsh4[o*4+2] + bsh4[o*4+3]);
    }

    #pragma unroll
    for (int i = 0; i < 4; i++) {
        size_t off = ((size_t)b*FOUT + o0 + i)*HW + p_base + p0;
        float4 old0 = *(const float4*)(embs_t + off);
        float4 old1 = *(const float4*)(embs_t + off + 4);
        float4 r0, r1;
        r0.x = old0.x + acc[i][0] + beff[i];
        r0.y = old0.y + acc[i][1] + beff[i];
        r0.z = old0.z + acc[i][2] + beff[i];
        r0.w = old0.w + acc[i][3] + beff[i];
        r1.x = old1.x + acc[i][4] + beff[i];
        r1.y = old1.y + acc[i][5] + beff[i];
        r1.z = old1.z + acc[i][6] + beff[i];
        r1.w = old1.w + acc[i][7] + beff[i];
        *(float4*)(embs_t1 + off)     = r0;
        *(float4*)(embs_t1 + off + 4) = r1;
    }
}

// ---------------------------------------------------------------------------
// finalize: clipped + raw from embs[16][:, :3]
// ---------------------------------------------------------------------------
__global__ void k_final(const float* __restrict__ embs16,
                        float* __restrict__ clipd,
                        float* __restrict__ rawd) {
    int idx = blockIdx.x * blockDim.x + threadIdx.x;
    if (idx >= CLIP_N) return;
    int b   = idx / (3*HW);
    int rem = idx - b*(3*HW);
    int c   = rem >> 12;
    int pix = rem & 4095;
    float v = embs16[((size_t)b*FOUT + c)*HW + pix];
    rawd[idx]  = v;
    clipd[idx] = fminf(fmaxf(v, -1.0f), 1.0f);
}

// ---------------------------------------------------------------------------
extern "C" void kernel_launch(void* const* d_in, const int* in_sizes, int n_in,
                              void* d_out, int out_size) {
    const float* lat = (const float*)d_in[0];
    const float* Wk  = (const float*)d_in[1];
    const float* bk  = (const float*)d_in[2];
    const float* Wb  = (const float*)d_in[3];
    const float* bb  = (const float*)d_in[4];
    const float* lf  = (const float*)d_in[5];

    float* outp  = (float*)d_out;
    float* clipd = outp;
    float* embs  = outp + CLIP_N;
    float* rawd  = outp + CLIP_N + EMBS_N;

    cudaFuncSetAttribute(k_gemm, cudaFuncAttributeMaxDynamicSharedMemorySize, SMEM_GEMM);

    // launch order: 0 init, 1 prep, 2 stats, 3 gemm, 4 stats, 5 gemm
    //               → ncu -s 5 -c 1 captures k_gemm
    k_init<<<4096, 1024>>>(embs);
    k_prep<<<49, 256>>>(lat, Wk, bk, Wb, bb);

    for (int t = 0; t < NCALLS; t++) {
        const float* et  = embs + (long long)t * SLICE_N;
        float*       et1 = embs + (long long)(t+1) * SLICE_N;
        k_stats<<<dim3(FOUT, B), 256>>>(et);
        k_gemm <<<dim3(HW/TP, B), 256, SMEM_GEMM>>>(et, et1, lf);
    }
    k_final<<<(CLIP_N + 255)/256, 256>>>(embs + (long long)NCALLS * SLICE_N, clipd, rawd);
}